// round 12
// baseline (speedup 1.0000x reference)
#include <cuda_runtime.h>
#include <cuda_bf16.h>
#include <math.h>
#include <stdint.h>

#define NN 50000
#define NE 800000

// ---------------- scratch (device globals; allocation-free rule) -----------
__device__ float g_bufA[NN * 64];
__device__ float g_bufB[NN * 64];
__device__ int   g_cnt[NN];
__device__ int   g_start[NN];
__device__ int   g_rank[NE];
__device__ int   g_total;
__device__ int2  g_edge[NE];   // packed (col, weight-bits)

// ---------------------------------------------------------------------------
// CSR build (rank-based, atomic-free scatter) — runs concurrent with GEMM1
// ---------------------------------------------------------------------------
__global__ void zero_cnt_kernel() {
    int i = blockIdx.x * blockDim.x + threadIdx.x;
    if (i < NN) g_cnt[i] = 0;
    if (i == 0) g_total = 0;
}

__global__ void hist_rank_kernel(const int* __restrict__ row) {
    int e = blockIdx.x * blockDim.x + threadIdx.x;
    if (e < NE) g_rank[e] = atomicAdd(&g_cnt[row[e]], 1);
}

__global__ __launch_bounds__(256) void offsets_kernel() {
    __shared__ int sp[256];
    __shared__ int base;
    const int t = threadIdx.x;
    const int r = blockIdx.x * 256 + t;
    int c = (r < NN) ? g_cnt[r] : 0;
    sp[t] = c;
    __syncthreads();
    #pragma unroll
    for (int off = 1; off < 256; off <<= 1) {
        int v = (t >= off) ? sp[t - off] : 0;
        __syncthreads();
        sp[t] += v;
        __syncthreads();
    }
    if (t == 255) base = atomicAdd(&g_total, sp[255]);
    __syncthreads();
    if (r < NN) g_start[r] = base + sp[t] - c;
}

__global__ void scatter_kernel(const int* __restrict__ row,
                               const int* __restrict__ col,
                               const float* __restrict__ ew) {
    int e = blockIdx.x * blockDim.x + threadIdx.x;
    if (e < NE) {
        int p = g_start[row[e]] + g_rank[e];
        g_edge[p] = make_int2(col[e], __float_as_int(ew[e]));
    }
}

// ---------------------------------------------------------------------------
// Shared gather: warp accumulates its row (64-wide input, float2 per lane)
// ---------------------------------------------------------------------------
__device__ __forceinline__ float2 gather_row64(
    const float2* __restrict__ sup, int warp, int lane)
{
    int s = g_start[warp];
    int e = s + g_cnt[warp];
    float2 acc = make_float2(0.f, 0.f);
    int i = s;
    for (; i + 4 <= e; i += 4) {
        int2 c0 = g_edge[i + 0];
        int2 c1 = g_edge[i + 1];
        int2 c2 = g_edge[i + 2];
        int2 c3 = g_edge[i + 3];
        float2 v0 = sup[(size_t)c0.x * 32 + lane];
        float2 v1 = sup[(size_t)c1.x * 32 + lane];
        float2 v2 = sup[(size_t)c2.x * 32 + lane];
        float2 v3 = sup[(size_t)c3.x * 32 + lane];
        float w0 = __int_as_float(c0.y), w1 = __int_as_float(c1.y);
        float w2 = __int_as_float(c2.y), w3 = __int_as_float(c3.y);
        acc.x = fmaf(v0.x, w0, acc.x); acc.y = fmaf(v0.y, w0, acc.y);
        acc.x = fmaf(v1.x, w1, acc.x); acc.y = fmaf(v1.y, w1, acc.y);
        acc.x = fmaf(v2.x, w2, acc.x); acc.y = fmaf(v2.y, w2, acc.y);
        acc.x = fmaf(v3.x, w3, acc.x); acc.y = fmaf(v3.y, w3, acc.y);
    }
    for (; i < e; i++) {
        int2 c = g_edge[i];
        float2 v = sup[(size_t)c.x * 32 + lane];
        float w = __int_as_float(c.y);
        acc.x = fmaf(v.x, w, acc.x);
        acc.y = fmaf(v.y, w, acc.y);
    }
    return acc;
}

// ---------------------------------------------------------------------------
// Fused SpMM + (relu?) + dense matvec (x W + b): one warp per row.
// Input D=64. NOUT in {64, 40}. W is [64, NOUT] row-major, resident in smem.
// Matvec is exact fp32 — replaces a whole gemm launch + buffer round-trip.
// ---------------------------------------------------------------------------
template <int NOUT, bool RELU>
__global__ __launch_bounds__(256) void spmm_matvec_kernel(
    const float2* __restrict__ sup, const float* __restrict__ W,
    const float* __restrict__ bias, float2* __restrict__ out)
{
    __shared__ float Ws[64 * NOUT];
    __shared__ float hrow[8][66];

    const int tid  = threadIdx.x;
    const int wid  = tid >> 5;
    const int lane = tid & 31;

    #pragma unroll 4
    for (int i = tid; i < 64 * NOUT; i += 256) Ws[i] = W[i];
    __syncthreads();

    int warp = blockIdx.x * 8 + wid;
    if (warp >= NN) return;

    float2 acc = gather_row64(sup, warp, lane);
    if (RELU) {
        acc.x = fmaxf(acc.x, 0.f);
        acc.y = fmaxf(acc.y, 0.f);
    }
    hrow[wid][2 * lane]     = acc.x;
    hrow[wid][2 * lane + 1] = acc.y;
    __syncwarp();

    if (2 * lane < NOUT) {
        float2 o = *reinterpret_cast<const float2*>(bias + 2 * lane);
        const float* hp = hrow[wid];
        #pragma unroll 16
        for (int k = 0; k < 64; k++) {
            float hk = hp[k];
            float2 w = *reinterpret_cast<const float2*>(&Ws[k * NOUT + 2 * lane]);
            o.x = fmaf(hk, w.x, o.x);
            o.y = fmaf(hk, w.y, o.y);
        }
        out[(size_t)warp * (NOUT / 2) + lane] = o;
    }
}

// ---------------------------------------------------------------------------
// Final SpMM (40-wide) + fused log-softmax -> d_out
// ---------------------------------------------------------------------------
__global__ __launch_bounds__(256) void spmm_logsoftmax_kernel(
    const float2* __restrict__ sup, float2* __restrict__ out)
{
    int warp = (blockIdx.x * blockDim.x + threadIdx.x) >> 5;
    if (warp >= NN) return;
    const int lane = threadIdx.x & 31;
    const bool act = lane < 20;
    int s = g_start[warp];
    int e = s + g_cnt[warp];

    float2 acc = make_float2(0.f, 0.f);
    int i = s;
    for (; i + 4 <= e; i += 4) {
        int2 c0 = g_edge[i + 0];
        int2 c1 = g_edge[i + 1];
        int2 c2 = g_edge[i + 2];
        int2 c3 = g_edge[i + 3];
        if (act) {
            float2 v0 = sup[(size_t)c0.x * 20 + lane];
            float2 v1 = sup[(size_t)c1.x * 20 + lane];
            float2 v2 = sup[(size_t)c2.x * 20 + lane];
            float2 v3 = sup[(size_t)c3.x * 20 + lane];
            float w0 = __int_as_float(c0.y), w1 = __int_as_float(c1.y);
            float w2 = __int_as_float(c2.y), w3 = __int_as_float(c3.y);
            acc.x = fmaf(v0.x, w0, acc.x); acc.y = fmaf(v0.y, w0, acc.y);
            acc.x = fmaf(v1.x, w1, acc.x); acc.y = fmaf(v1.y, w1, acc.y);
            acc.x = fmaf(v2.x, w2, acc.x); acc.y = fmaf(v2.y, w2, acc.y);
            acc.x = fmaf(v3.x, w3, acc.x); acc.y = fmaf(v3.y, w3, acc.y);
        }
    }
    for (; i < e; i++) {
        int2 c = g_edge[i];
        if (act) {
            float2 v = sup[(size_t)c.x * 20 + lane];
            float w = __int_as_float(c.y);
            acc.x = fmaf(v.x, w, acc.x);
            acc.y = fmaf(v.y, w, acc.y);
        }
    }

    float mv = act ? fmaxf(acc.x, acc.y) : -INFINITY;
    #pragma unroll
    for (int o = 16; o; o >>= 1) mv = fmaxf(mv, __shfl_xor_sync(0xffffffffu, mv, o));
    float sv = act ? (expf(acc.x - mv) + expf(acc.y - mv)) : 0.f;
    #pragma unroll
    for (int o = 16; o; o >>= 1) sv += __shfl_xor_sync(0xffffffffu, sv, o);
    float ls = mv + logf(sv);
    if (act) out[(size_t)warp * 20 + lane] = make_float2(acc.x - ls, acc.y - ls);
}

// ---------------------------------------------------------------------------
// Split-bf16 tensor-core GEMM — only used for GEMM1 (K=512)
// ---------------------------------------------------------------------------
#define SROW 24

__device__ __forceinline__ unsigned pack_bf16(float a, float b) {
    __nv_bfloat162 t = __floats2bfloat162_rn(a, b);
    return *reinterpret_cast<unsigned*>(&t);
}

__device__ __forceinline__ void mma16816(float* c, const unsigned* a, const unsigned* b) {
    asm volatile(
        "mma.sync.aligned.m16n8k16.row.col.f32.bf16.bf16.f32 "
        "{%0,%1,%2,%3}, {%4,%5,%6,%7}, {%8,%9}, {%0,%1,%2,%3};"
        : "+f"(c[0]), "+f"(c[1]), "+f"(c[2]), "+f"(c[3])
        : "r"(a[0]), "r"(a[1]), "r"(a[2]), "r"(a[3]), "r"(b[0]), "r"(b[1]));
}

__global__ __launch_bounds__(256) void gemm_mma_kernel(
    const float* __restrict__ A, const float* __restrict__ B,
    const float* __restrict__ bias, float* __restrict__ C,
    int M, int K, int N)
{
    __shared__ __nv_bfloat16 Ah[2][128 * SROW], Al[2][128 * SROW];
    __shared__ __nv_bfloat16 Bh[2][64 * SROW],  Bl[2][64 * SROW];

    const int tid  = threadIdx.x;
    const int m0   = blockIdx.x * 128;
    const int wid  = tid >> 5;
    const int lane = tid & 31;
    const int wm = (wid & 3) * 32;
    const int wn = (wid >> 2) * 32;
    const int qm = lane >> 2;
    const int qk = lane & 3;

    const int arow = tid >> 1;
    const int akh  = (tid & 1) * 8;
    const bool aok = (m0 + arow) < M;
    const float* Aptr = A + (size_t)(m0 + arow) * K + akh;

    const int bk = tid >> 4;
    const int bn = (tid * 4) & 63;

    float av[8];
    float bv[4];
    float acc[2][4][4] = {};

    const int S = K / 16;

    auto load_regs = [&](int k0) {
        if (aok) {
            float4 v0 = *reinterpret_cast<const float4*>(Aptr + k0);
            float4 v1 = *reinterpret_cast<const float4*>(Aptr + k0 + 4);
            av[0] = v0.x; av[1] = v0.y; av[2] = v0.z; av[3] = v0.w;
            av[4] = v1.x; av[5] = v1.y; av[6] = v1.z; av[7] = v1.w;
        } else {
            #pragma unroll
            for (int i = 0; i < 8; i++) av[i] = 0.f;
        }
        #pragma unroll
        for (int j = 0; j < 4; j++) {
            int n = bn + j;
            bv[j] = (n < N) ? B[(size_t)(k0 + bk) * N + n] : 0.f;
        }
    };

    auto store_stage = [&](int st) {
        float lo[8];
        unsigned h[4], l[4];
        #pragma unroll
        for (int i = 0; i < 8; i++) {
            __nv_bfloat16 hb = __float2bfloat16_rn(av[i]);
            lo[i] = av[i] - __bfloat162float(hb);
        }
        #pragma unroll
        for (int p = 0; p < 4; p++) {
            h[p] = pack_bf16(av[2 * p], av[2 * p + 1]);
            l[p] = pack_bf16(lo[2 * p], lo[2 * p + 1]);
        }
        *reinterpret_cast<uint4*>(&Ah[st][arow * SROW + akh]) = make_uint4(h[0], h[1], h[2], h[3]);
        *reinterpret_cast<uint4*>(&Al[st][arow * SROW + akh]) = make_uint4(l[0], l[1], l[2], l[3]);
        #pragma unroll
        for (int j = 0; j < 4; j++) {
            __nv_bfloat16 hb = __float2bfloat16_rn(bv[j]);
            float lf = bv[j] - __bfloat162float(hb);
            Bh[st][(bn + j) * SROW + bk] = hb;
            Bl[st][(bn + j) * SROW + bk] = __float2bfloat16_rn(lf);
        }
    };

    load_regs(0);
    store_stage(0);
    __syncthreads();

    for (int s = 0; s < S; s++) {
        const int cur = s & 1;
        if (s + 1 < S) load_regs((s + 1) * 16);

        unsigned ah[2][4], al[2][4], bh[4][2], bl[4][2];
        #pragma unroll
        for (int i = 0; i < 2; i++) {
            int r = (wm + i * 16 + qm) * SROW;
            ah[i][0] = *reinterpret_cast<unsigned*>(&Ah[cur][r + qk * 2]);
            ah[i][1] = *reinterpret_cast<unsigned*>(&Ah[cur][r + 8 * SROW + qk * 2]);
            ah[i][2] = *reinterpret_cast<unsigned*>(&Ah[cur][r + 8 + qk * 2]);
            ah[i][3] = *reinterpret_cast<unsigned*>(&Ah[cur][r + 8 * SROW + 8 + qk * 2]);
            al[i][0] = *reinterpret_cast<unsigned*>(&Al[cur][r + qk * 2]);
            al[i][1] = *reinterpret_cast<unsigned*>(&Al[cur][r + 8 * SROW + qk * 2]);
            al[i][2] = *reinterpret_cast<unsigned*>(&Al[cur][r + 8 + qk * 2]);
            al[i][3] = *reinterpret_cast<unsigned*>(&Al[cur][r + 8 * SROW + 8 + qk * 2]);
        }
        #pragma unroll
        for (int j = 0; j < 4; j++) {
            int r = (wn + j * 8 + qm) * SROW;
            bh[j][0] = *reinterpret_cast<unsigned*>(&Bh[cur][r + qk * 2]);
            bh[j][1] = *reinterpret_cast<unsigned*>(&Bh[cur][r + 8 + qk * 2]);
            bl[j][0] = *reinterpret_cast<unsigned*>(&Bl[cur][r + qk * 2]);
            bl[j][1] = *reinterpret_cast<unsigned*>(&Bl[cur][r + 8 + qk * 2]);
        }

        #pragma unroll
        for (int i = 0; i < 2; i++)
            #pragma unroll
            for (int j = 0; j < 4; j++) {
                mma16816(acc[i][j], ah[i], bh[j]);
                mma16816(acc[i][j], ah[i], bl[j]);
                mma16816(acc[i][j], al[i], bh[j]);
            }

        if (s + 1 < S) {
            store_stage(cur ^ 1);
            __syncthreads();
        }
    }

    #pragma unroll
    for (int j = 0; j < 4; j++) {
        int c0 = wn + j * 8 + (lane & 3) * 2;
        if (c0 >= N) continue;
        float b0 = bias[c0], b1 = bias[c0 + 1];
        #pragma unroll
        for (int i = 0; i < 2; i++) {
            int r0 = m0 + wm + i * 16 + (lane >> 2);
            if (r0 < M) {
                float2 o = make_float2(acc[i][j][0] + b0, acc[i][j][1] + b1);
                *reinterpret_cast<float2*>(C + (size_t)r0 * N + c0) = o;
            }
            if (r0 + 8 < M) {
                float2 o = make_float2(acc[i][j][2] + b0, acc[i][j][3] + b1);
                *reinterpret_cast<float2*>(C + (size_t)(r0 + 8) * N + c0) = o;
            }
        }
    }
}

// ---------------------------------------------------------------------------
// launch: CSR ∥ GEMM1, then 3 fused spmm kernels.
//   gemm1: x -> A (s1)
//   F1: spmm(A)+relu, ×W2+b2 -> B (s2)
//   F2: spmm(B), ×W3+b3 -> A (s3, 40-wide)
//   F3: spmm(A) + log-softmax -> out
// ---------------------------------------------------------------------------
extern "C" void kernel_launch(void* const* d_in, const int* in_sizes, int n_in,
                              void* d_out, int out_size)
{
    const float* x   = (const float*)d_in[0];
    const float* ew  = (const float*)d_in[1];
    const float* W1  = (const float*)d_in[2];
    const float* b1  = (const float*)d_in[3];
    const float* W2  = (const float*)d_in[4];
    const float* b2  = (const float*)d_in[5];
    const float* W3  = (const float*)d_in[6];
    const float* b3  = (const float*)d_in[7];
    const int*   row = (const int*)d_in[8];
    const int*   col = (const int*)d_in[9];
    float* out = (float*)d_out;

    float *bufA, *bufB;
    cudaGetSymbolAddress((void**)&bufA, g_bufA);
    cudaGetSymbolAddress((void**)&bufB, g_bufB);

    const int gemmBlocks = (NN + 127) / 128;          // 391
    const int edgeBlocks = (NE + 255) / 256;          // 3125
    const int rowBlocks  = (NN + 255) / 256;          // 196
    const int rowWarpBlocks = (NN + 7) / 8;           // 6250 (8 warps/block)

    cudaStream_t s2;
    cudaStreamCreate(&s2);
    cudaEvent_t evFork, evCSR;
    cudaEventCreateWithFlags(&evFork, cudaEventDisableTiming);
    cudaEventCreateWithFlags(&evCSR,  cudaEventDisableTiming);

    cudaEventRecord(evFork, 0);
    cudaStreamWaitEvent(s2, evFork, 0);

    // s2: CSR build (concurrent with GEMM1)
    zero_cnt_kernel<<<rowBlocks, 256, 0, s2>>>();
    hist_rank_kernel<<<edgeBlocks, 256, 0, s2>>>(row);
    offsets_kernel<<<rowBlocks, 256, 0, s2>>>();
    scatter_kernel<<<edgeBlocks, 256, 0, s2>>>(row, col, ew);
    cudaEventRecord(evCSR, s2);

    // main: GEMM1 -> A
    gemm_mma_kernel<<<gemmBlocks, 256>>>(x, W1, b1, bufA, NN, 512, 64);
    cudaStreamWaitEvent(0, evCSR, 0);

    // F1: spmm + relu + ×W2 -> B
    spmm_matvec_kernel<64, true><<<rowWarpBlocks, 256>>>(
        (const float2*)bufA, W2, b2, (float2*)bufB);
    // F2: spmm + ×W3 -> A (40-wide)
    spmm_matvec_kernel<40, false><<<rowWarpBlocks, 256>>>(
        (const float2*)bufB, W3, b3, (float2*)bufA);
    // F3: spmm + log-softmax -> out
    spmm_logsoftmax_kernel<<<rowWarpBlocks * 8 * 32 / 256, 256>>>(
        (const float2*)bufA, (float2*)out);

    cudaEventDestroy(evFork);
    cudaEventDestroy(evCSR);
    cudaStreamDestroy(s2);
}

// round 14
// speedup vs baseline: 1.1816x; 1.1816x over previous
#include <cuda_runtime.h>
#include <cuda_bf16.h>
#include <math.h>
#include <stdint.h>

#define NN 50000
#define NE 800000

// ---------------- scratch (device globals; allocation-free rule) -----------
__device__ __nv_bfloat16 g_bufS[NN * 64];   // support (gemm out, gathered by spmm)
__device__ float         g_bufH[NN * 64];   // aggregated h (spmm out, gemm in)
__device__ int   g_cnt[NN];
__device__ int   g_start[NN];
__device__ int   g_rank[NE];
__device__ int   g_total;
__device__ int2  g_edge[NE];   // packed (col, weight-bits)

// ---------------------------------------------------------------------------
// CSR build (rank-based, atomic-free scatter) — concurrent with GEMM1
// ---------------------------------------------------------------------------
__global__ void zero_cnt_kernel() {
    int i = blockIdx.x * blockDim.x + threadIdx.x;
    if (i < NN) g_cnt[i] = 0;
    if (i == 0) g_total = 0;
}

__global__ void hist_rank_kernel(const int* __restrict__ row) {
    int e = blockIdx.x * blockDim.x + threadIdx.x;
    if (e < NE) g_rank[e] = atomicAdd(&g_cnt[row[e]], 1);
}

__global__ __launch_bounds__(256) void offsets_kernel() {
    __shared__ int sp[256];
    __shared__ int base;
    const int t = threadIdx.x;
    const int r = blockIdx.x * 256 + t;
    int c = (r < NN) ? g_cnt[r] : 0;
    sp[t] = c;
    __syncthreads();
    #pragma unroll
    for (int off = 1; off < 256; off <<= 1) {
        int v = (t >= off) ? sp[t - off] : 0;
        __syncthreads();
        sp[t] += v;
        __syncthreads();
    }
    if (t == 255) base = atomicAdd(&g_total, sp[255]);
    __syncthreads();
    if (r < NN) g_start[r] = base + sp[t] - c;
}

__global__ void scatter_kernel(const int* __restrict__ row,
                               const int* __restrict__ col,
                               const float* __restrict__ ew) {
    int e = blockIdx.x * blockDim.x + threadIdx.x;
    if (e < NE) {
        int p = g_start[row[e]] + g_rank[e];
        g_edge[p] = make_int2(col[e], __float_as_int(ew[e]));
    }
}

// ---------------------------------------------------------------------------
// SpMM via CSR, warp per row; support rows are bf16 (half the gather bytes).
// NF2 = bf16x2 (and output float2) per row: 32 for D=64, 20 for D=40.
// LOGSM: fuse log-softmax over D=40 into the epilogue (writes final output).
// fp32 accumulators + fp32 edge weights.
// ---------------------------------------------------------------------------
template <int NF2, bool LOGSM>
__global__ __launch_bounds__(256) void spmm_csr_kernel(
    const __nv_bfloat162* __restrict__ sup, float2* __restrict__ out)
{
    int warp = (blockIdx.x * blockDim.x + threadIdx.x) >> 5;
    if (warp >= NN) return;
    const int lane = threadIdx.x & 31;
    const bool act = (NF2 == 32) || (lane < NF2);
    int s = g_start[warp];
    int e = s + g_cnt[warp];

    float2 acc = make_float2(0.f, 0.f);
    int i = s;
    for (; i + 4 <= e; i += 4) {
        int2 c0 = g_edge[i + 0];
        int2 c1 = g_edge[i + 1];
        int2 c2 = g_edge[i + 2];
        int2 c3 = g_edge[i + 3];
        if (act) {
            float2 v0 = __bfloat1622float2(sup[(size_t)c0.x * NF2 + lane]);
            float2 v1 = __bfloat1622float2(sup[(size_t)c1.x * NF2 + lane]);
            float2 v2 = __bfloat1622float2(sup[(size_t)c2.x * NF2 + lane]);
            float2 v3 = __bfloat1622float2(sup[(size_t)c3.x * NF2 + lane]);
            float w0 = __int_as_float(c0.y), w1 = __int_as_float(c1.y);
            float w2 = __int_as_float(c2.y), w3 = __int_as_float(c3.y);
            acc.x = fmaf(v0.x, w0, acc.x); acc.y = fmaf(v0.y, w0, acc.y);
            acc.x = fmaf(v1.x, w1, acc.x); acc.y = fmaf(v1.y, w1, acc.y);
            acc.x = fmaf(v2.x, w2, acc.x); acc.y = fmaf(v2.y, w2, acc.y);
            acc.x = fmaf(v3.x, w3, acc.x); acc.y = fmaf(v3.y, w3, acc.y);
        }
    }
    for (; i < e; i++) {
        int2 c = g_edge[i];
        if (act) {
            float2 v = __bfloat1622float2(sup[(size_t)c.x * NF2 + lane]);
            float w = __int_as_float(c.y);
            acc.x = fmaf(v.x, w, acc.x);
            acc.y = fmaf(v.y, w, acc.y);
        }
    }

    if (!LOGSM) {
        if (act) out[(size_t)warp * NF2 + lane] = acc;
    } else {
        float mv = act ? fmaxf(acc.x, acc.y) : -INFINITY;
        #pragma unroll
        for (int o = 16; o; o >>= 1) mv = fmaxf(mv, __shfl_xor_sync(0xffffffffu, mv, o));
        float sv = act ? (expf(acc.x - mv) + expf(acc.y - mv)) : 0.f;
        #pragma unroll
        for (int o = 16; o; o >>= 1) sv += __shfl_xor_sync(0xffffffffu, sv, o);
        float ls = mv + logf(sv);
        if (act) out[(size_t)warp * NF2 + lane] = make_float2(acc.x - ls, acc.y - ls);
    }
}

// ---------------------------------------------------------------------------
// Split-bf16 tensor-core GEMM; A fp32 (optionally relu'd), C written as bf16.
// ---------------------------------------------------------------------------
#define SROW 24

__device__ __forceinline__ unsigned pack_bf16(float a, float b) {
    __nv_bfloat162 t = __floats2bfloat162_rn(a, b);
    return *reinterpret_cast<unsigned*>(&t);
}

__device__ __forceinline__ void mma16816(float* c, const unsigned* a, const unsigned* b) {
    asm volatile(
        "mma.sync.aligned.m16n8k16.row.col.f32.bf16.bf16.f32 "
        "{%0,%1,%2,%3}, {%4,%5,%6,%7}, {%8,%9}, {%0,%1,%2,%3};"
        : "+f"(c[0]), "+f"(c[1]), "+f"(c[2]), "+f"(c[3])
        : "r"(a[0]), "r"(a[1]), "r"(a[2]), "r"(a[3]), "r"(b[0]), "r"(b[1]));
}

template <bool RELU>
__global__ __launch_bounds__(256) void gemm_mma_kernel(
    const float* __restrict__ A, const float* __restrict__ B,
    const float* __restrict__ bias, __nv_bfloat16* __restrict__ C,
    int M, int K, int N)
{
    __shared__ __nv_bfloat16 Ah[2][128 * SROW], Al[2][128 * SROW];
    __shared__ __nv_bfloat16 Bh[2][64 * SROW],  Bl[2][64 * SROW];

    const int tid  = threadIdx.x;
    const int m0   = blockIdx.x * 128;
    const int wid  = tid >> 5;
    const int lane = tid & 31;
    const int wm = (wid & 3) * 32;
    const int wn = (wid >> 2) * 32;
    const int qm = lane >> 2;
    const int qk = lane & 3;

    const int arow = tid >> 1;
    const int akh  = (tid & 1) * 8;
    const bool aok = (m0 + arow) < M;
    const float* Aptr = A + (size_t)(m0 + arow) * K + akh;

    const int bk = tid >> 4;
    const int bn = (tid * 4) & 63;

    float av[8];
    float bv[4];
    float acc[2][4][4] = {};

    const int S = K / 16;

    auto load_regs = [&](int k0) {
        if (aok) {
            float4 v0 = *reinterpret_cast<const float4*>(Aptr + k0);
            float4 v1 = *reinterpret_cast<const float4*>(Aptr + k0 + 4);
            av[0] = v0.x; av[1] = v0.y; av[2] = v0.z; av[3] = v0.w;
            av[4] = v1.x; av[5] = v1.y; av[6] = v1.z; av[7] = v1.w;
            if (RELU) {
                #pragma unroll
                for (int i = 0; i < 8; i++) av[i] = fmaxf(av[i], 0.f);
            }
        } else {
            #pragma unroll
            for (int i = 0; i < 8; i++) av[i] = 0.f;
        }
        #pragma unroll
        for (int j = 0; j < 4; j++) {
            int n = bn + j;
            bv[j] = (n < N) ? B[(size_t)(k0 + bk) * N + n] : 0.f;
        }
    };

    auto store_stage = [&](int st) {
        float lo[8];
        unsigned h[4], l[4];
        #pragma unroll
        for (int i = 0; i < 8; i++) {
            __nv_bfloat16 hb = __float2bfloat16_rn(av[i]);
            lo[i] = av[i] - __bfloat162float(hb);
        }
        #pragma unroll
        for (int p = 0; p < 4; p++) {
            h[p] = pack_bf16(av[2 * p], av[2 * p + 1]);
            l[p] = pack_bf16(lo[2 * p], lo[2 * p + 1]);
        }
        *reinterpret_cast<uint4*>(&Ah[st][arow * SROW + akh]) = make_uint4(h[0], h[1], h[2], h[3]);
        *reinterpret_cast<uint4*>(&Al[st][arow * SROW + akh]) = make_uint4(l[0], l[1], l[2], l[3]);
        #pragma unroll
        for (int j = 0; j < 4; j++) {
            __nv_bfloat16 hb = __float2bfloat16_rn(bv[j]);
            float lf = bv[j] - __bfloat162float(hb);
            Bh[st][(bn + j) * SROW + bk] = hb;
            Bl[st][(bn + j) * SROW + bk] = __float2bfloat16_rn(lf);
        }
    };

    load_regs(0);
    store_stage(0);
    __syncthreads();

    for (int s = 0; s < S; s++) {
        const int cur = s & 1;
        if (s + 1 < S) load_regs((s + 1) * 16);

        unsigned ah[2][4], al[2][4], bh[4][2], bl[4][2];
        #pragma unroll
        for (int i = 0; i < 2; i++) {
            int r = (wm + i * 16 + qm) * SROW;
            ah[i][0] = *reinterpret_cast<unsigned*>(&Ah[cur][r + qk * 2]);
            ah[i][1] = *reinterpret_cast<unsigned*>(&Ah[cur][r + 8 * SROW + qk * 2]);
            ah[i][2] = *reinterpret_cast<unsigned*>(&Ah[cur][r + 8 + qk * 2]);
            ah[i][3] = *reinterpret_cast<unsigned*>(&Ah[cur][r + 8 * SROW + 8 + qk * 2]);
            al[i][0] = *reinterpret_cast<unsigned*>(&Al[cur][r + qk * 2]);
            al[i][1] = *reinterpret_cast<unsigned*>(&Al[cur][r + 8 * SROW + qk * 2]);
            al[i][2] = *reinterpret_cast<unsigned*>(&Al[cur][r + 8 + qk * 2]);
            al[i][3] = *reinterpret_cast<unsigned*>(&Al[cur][r + 8 * SROW + 8 + qk * 2]);
        }
        #pragma unroll
        for (int j = 0; j < 4; j++) {
            int r = (wn + j * 8 + qm) * SROW;
            bh[j][0] = *reinterpret_cast<unsigned*>(&Bh[cur][r + qk * 2]);
            bh[j][1] = *reinterpret_cast<unsigned*>(&Bh[cur][r + 8 + qk * 2]);
            bl[j][0] = *reinterpret_cast<unsigned*>(&Bl[cur][r + qk * 2]);
            bl[j][1] = *reinterpret_cast<unsigned*>(&Bl[cur][r + 8 + qk * 2]);
        }

        #pragma unroll
        for (int i = 0; i < 2; i++)
            #pragma unroll
            for (int j = 0; j < 4; j++) {
                mma16816(acc[i][j], ah[i], bh[j]);
                mma16816(acc[i][j], ah[i], bl[j]);
                mma16816(acc[i][j], al[i], bh[j]);
            }

        if (s + 1 < S) {
            store_stage(cur ^ 1);
            __syncthreads();
        }
    }

    // epilogue: bias add, write bf16x2
    #pragma unroll
    for (int j = 0; j < 4; j++) {
        int c0 = wn + j * 8 + (lane & 3) * 2;
        if (c0 >= N) continue;
        float b0 = bias[c0], b1 = bias[c0 + 1];
        #pragma unroll
        for (int i = 0; i < 2; i++) {
            int r0 = m0 + wm + i * 16 + (lane >> 2);
            if (r0 < M) {
                __nv_bfloat162 o = __floats2bfloat162_rn(acc[i][j][0] + b0,
                                                         acc[i][j][1] + b1);
                *reinterpret_cast<__nv_bfloat162*>(C + (size_t)r0 * N + c0) = o;
            }
            if (r0 + 8 < M) {
                __nv_bfloat162 o = __floats2bfloat162_rn(acc[i][j][2] + b0,
                                                         acc[i][j][3] + b1);
                *reinterpret_cast<__nv_bfloat162*>(C + (size_t)(r0 + 8) * N + c0) = o;
            }
        }
    }
}

// ---------------------------------------------------------------------------
// launch: CSR ∥ GEMM1, then serial layers (R11 structure).
//   gemm1: x (f32) -> S (bf16) ; spmm1: S -> H (f32) ;
//   gemm2: H -> S ; spmm2: S -> H ; gemm3: H -> S (40) ;
//   spmm3+logsoftmax: S -> out (f32)
// ---------------------------------------------------------------------------
extern "C" void kernel_launch(void* const* d_in, const int* in_sizes, int n_in,
                              void* d_out, int out_size)
{
    const float* x   = (const float*)d_in[0];
    const float* ew  = (const float*)d_in[1];
    const float* W1  = (const float*)d_in[2];
    const float* b1  = (const float*)d_in[3];
    const float* W2  = (const float*)d_in[4];
    const float* b2  = (const float*)d_in[5];
    const float* W3  = (const float*)d_in[6];
    const float* b3  = (const float*)d_in[7];
    const int*   row = (const int*)d_in[8];
    const int*   col = (const int*)d_in[9];
    float* out = (float*)d_out;

    __nv_bfloat16 *bufS;
    float *bufH;
    cudaGetSymbolAddress((void**)&bufS, g_bufS);
    cudaGetSymbolAddress((void**)&bufH, g_bufH);

    const int gemmBlocks = (NN + 127) / 128;          // 391
    const int edgeBlocks = (NE + 255) / 256;          // 3125
    const int rowBlocks  = (NN + 255) / 256;          // 196
    const int rowWarpBlocks = (NN * 32 + 255) / 256;  // 6250

    cudaStream_t s2;
    cudaStreamCreate(&s2);
    cudaEvent_t evFork, evCSR;
    cudaEventCreateWithFlags(&evFork, cudaEventDisableTiming);
    cudaEventCreateWithFlags(&evCSR,  cudaEventDisableTiming);

    cudaEventRecord(evFork, 0);
    cudaStreamWaitEvent(s2, evFork, 0);

    // s2: CSR build (concurrent with GEMM1)
    zero_cnt_kernel<<<rowBlocks, 256, 0, s2>>>();
    hist_rank_kernel<<<edgeBlocks, 256, 0, s2>>>(row);
    offsets_kernel<<<rowBlocks, 256, 0, s2>>>();
    scatter_kernel<<<edgeBlocks, 256, 0, s2>>>(row, col, ew);
    cudaEventRecord(evCSR, s2);

    // main: GEMM1 -> S (bf16)
    gemm_mma_kernel<false><<<gemmBlocks, 256>>>(x, W1, b1, bufS, NN, 512, 64);
    cudaStreamWaitEvent(0, evCSR, 0);

    // layer 1: spmm S -> H
    spmm_csr_kernel<32, false><<<rowWarpBlocks, 256>>>(
        (const __nv_bfloat162*)bufS, (float2*)bufH);
    // layer 2: gemm (relu on A) H -> S ; spmm S -> H
    gemm_mma_kernel<true><<<gemmBlocks, 256>>>(bufH, W2, b2, bufS, NN, 64, 64);
    spmm_csr_kernel<32, false><<<rowWarpBlocks, 256>>>(
        (const __nv_bfloat162*)bufS, (float2*)bufH);
    // layer 3: gemm H -> S (40) ; spmm + log-softmax -> out
    gemm_mma_kernel<false><<<gemmBlocks, 256>>>(bufH, W3, b3, bufS, NN, 64, 40);
    spmm_csr_kernel<20, true><<<rowWarpBlocks, 256>>>(
        (const __nv_bfloat162*)bufS, (float2*)out);

    cudaEventDestroy(evFork);
    cudaEventDestroy(evCSR);
    cudaStreamDestroy(s2);
}